// round 12
// baseline (speedup 1.0000x reference)
#include <cuda_runtime.h>
#include <cuda_bf16.h>
#include <math.h>
#include <stdint.h>

#define R_TOT 16384
#define NE    8192
#define DDIM  256
#define NCAND 24          // 8 subslots x top-3
#define NSTG  3           // 16KB stages
#define STG_BYTES 16384
#define SMEM_TOT (NSTG * STG_BYTES)
#define NSI   256         // stage-iters per CTA (each = half tile, k=128)

constexpr long O_LOSS = 0;
constexpr long O_ZQ   = 1;
constexpr long O_PERP = 4194305;
constexpr long O_ENC  = 4194306;
constexpr long O_MIN  = 138412034;
constexpr long O_SEC  = 138428418;

__device__ double g_loss;
__device__ double g_H;
__device__ int    g_counts[NE];
__device__ float  g_A[R_TOT];
__device__ int    g_cand[R_TOT * NCAND];
__device__ __nv_bfloat16 g_zb[R_TOT * DDIM];   // z, row-major bf16
__device__ __nv_bfloat16 g_eb[NE * DDIM];      // embedding bf16

// ---------------- PTX helpers (sm_80-era only) ----------------
__device__ __forceinline__ uint32_t smem_u32(const void* p) {
    uint32_t a;
    asm("{ .reg .u64 t; cvta.to.shared.u64 t, %1; cvt.u32.u64 %0, t; }" : "=r"(a) : "l"(p));
    return a;
}
#define CPA16(sa, g) asm volatile("cp.async.cg.shared.global [%0], [%1], 16;" :: "r"(sa), "l"(g) : "memory")
#define CP_COMMIT()  asm volatile("cp.async.commit_group;" ::: "memory")
#define CP_WAIT1()   asm volatile("cp.async.wait_group 1;" ::: "memory")

__device__ __forceinline__ void ldsm4(uint32_t* r, uint32_t addr) {
    asm volatile("ldmatrix.sync.aligned.m8n8.x4.shared.b16 {%0,%1,%2,%3}, [%4];"
                 : "=r"(r[0]), "=r"(r[1]), "=r"(r[2]), "=r"(r[3]) : "r"(addr));
}
__device__ __forceinline__ void mma_bf16(float* c, const uint32_t* a, uint32_t b0, uint32_t b1) {
    asm volatile("mma.sync.aligned.m16n8k16.row.col.f32.bf16.bf16.f32 "
                 "{%0,%1,%2,%3}, {%4,%5,%6,%7}, {%8,%9}, {%0,%1,%2,%3};"
                 : "+f"(c[0]), "+f"(c[1]), "+f"(c[2]), "+f"(c[3])
                 : "r"(a[0]), "r"(a[1]), "r"(a[2]), "r"(a[3]), "r"(b0), "r"(b1));
}

// ---------------- ordering (jax top_k: dist asc, index asc) ----------------
__device__ __forceinline__ bool lessp(float ad, int ai, float bd, int bi) {
    return (ad < bd) || (ad == bd && ai < bi);
}
__device__ __forceinline__ void ins2(float& d1, int& i1, float& d2, int& i2, float dd, int jj) {
    if (lessp(dd, jj, d1, i1)) { d2 = d1; i2 = i1; d1 = dd; i1 = jj; }
    else if (lessp(dd, jj, d2, i2)) { d2 = dd; i2 = jj; }
}
__device__ __forceinline__ void merge2(float& d1, int& i1, float& d2, int& i2,
                                       float od1, int oi1, float od2, int oi2) {
    if (lessp(od1, oi1, d1, i1)) {
        if (lessp(d1, i1, od2, oi2)) { d2 = d1; i2 = i1; } else { d2 = od2; i2 = oi2; }
        d1 = od1; i1 = oi1;
    } else if (lessp(od1, oi1, d2, i2)) { d2 = od1; i2 = oi1; }
}
__device__ __forceinline__ void top3_ins(float* tv, int* tj, float dd, int j) {
    if (dd < tv[2]) {
        if (dd < tv[1]) {
            tv[2] = tv[1]; tj[2] = tj[1];
            if (dd < tv[0]) { tv[1] = tv[0]; tj[1] = tj[0]; tv[0] = dd; tj[0] = j; }
            else { tv[1] = dd; tj[1] = j; }
        } else { tv[2] = dd; tj[2] = j; }
    }
}

// ---------------- K0: init (counts, scalars, g_A accumulators) -------------
__global__ void vq_init() {
    int i = blockIdx.x * blockDim.x + threadIdx.x;     // 16384 threads
    if (i < NE) g_counts[i] = 0;
    g_A[i] = 0.f;
    if (i == 0) { g_loss = 0.0; g_H = 0.0; }
}

// ---------------- K0b: emb -> bf16 ----------------
__global__ void vq_prep_emb(const float* __restrict__ emb) {
    int i = blockIdx.x * blockDim.x + threadIdx.x;
    float4 v = reinterpret_cast<const float4*>(emb)[i];
    __nv_bfloat16* o = g_eb + (long)i * 4;
    o[0] = __float2bfloat16_rn(v.x); o[1] = __float2bfloat16_rn(v.y);
    o[2] = __float2bfloat16_rn(v.z); o[3] = __float2bfloat16_rn(v.w);
}

// ---------------- K0c: z transpose -> bf16 row-major, + |z|^2 fold ---------
__global__ void vq_prep_z(const float* __restrict__ z) {
    __shared__ float s[32][33];
    __shared__ float rs[32];
    int bk = blockIdx.x;                 // 0..4095
    int bi = bk >> 8, cblk = (bk >> 5) & 7, hwblk = bk & 31;
    int t = threadIdx.x;
    int j = t & 31, i0 = t >> 5;
    if (t < 32) rs[t] = 0.f;
    __syncthreads();
    float p = 0.f;
    #pragma unroll
    for (int ii = 0; ii < 4; ii++) {
        int i = i0 + ii * 8;
        float v = z[(long)bi * 262144L + (long)(cblk * 32 + i) * 1024L + hwblk * 32 + j];
        s[i][j] = v;
        p = fmaf(v, v, p);
    }
    atomicAdd(&rs[j], p);
    __syncthreads();
    int cl = t & 31, j0 = t >> 5;
    #pragma unroll
    for (int ii = 0; ii < 4; ii++) {
        int j2 = j0 + ii * 8;
        g_zb[(long)(bi * 1024 + hwblk * 32 + j2) * DDIM + cblk * 32 + cl] =
            __float2bfloat16_rn(s[cl][j2]);
    }
    if (t < 32) atomicAdd(&g_A[bi * 1024 + hwblk * 32 + t], rs[t]);
}

// ---------------- K1: bf16 mma.sync GEMM, 512 thr, 16 warps (8 rowg x 2 cg) -
// stage si: tile = si>>1 (64 cols), k-half = si&1 (k 0..127 or 128..255)
__device__ __forceinline__ void loadB_stage(uint32_t sbB, int si, int slot, int tid) {
    int tile = si >> 1;
    int j0 = tile * 64;
    uint32_t base = sbB + (uint32_t)slot * STG_BYTES;
    #pragma unroll
    for (int r = 0; r < 2; r++) {
        int id = r * 512 + tid;          // 0..1023 16B units
        int c4 = id >> 8;                // k32-chunk within stage 0..3
        int u  = id & 255;
        int n  = u >> 2, c = u & 3;
        int kc = (si & 1) * 4 + c4;      // k32-chunk within tile 0..7
        const __nv_bfloat16* src = g_eb + (long)(j0 + n) * DDIM + kc * 32 + c * 8;
        uint32_t dst = base + c4 * 4096 + n * 64 + ((c ^ ((n >> 1) & 3)) << 4);
        CPA16(dst, src);
    }
}

__global__ void __launch_bounds__(512, 1) vq_gemm(float* __restrict__ out) {
    extern __shared__ __align__(128) char smem[];
    const uint32_t sbB = smem_u32(smem);
    const int tid = threadIdx.x, warp = tid >> 5, l = tid & 31;
    const int rowg = warp >> 1, cg = warp & 1;   // 8 row-groups x 2 col-groups
    const int rowbase = blockIdx.x * 128;

    loadB_stage(sbB, 0, 0, tid); CP_COMMIT();
    loadB_stage(sbB, 1, 1, tid); CP_COMMIT();

    // A fragments: this warp's 16 rows, full K=256 (16 k16-frags x 4 b32)
    uint32_t A4[16][4];
    const int r0l = l >> 2, c0l = (l & 3) * 2;
    {
        const __nv_bfloat16* zb = g_zb + (long)(rowbase + rowg * 16) * DDIM;
        #pragma unroll
        for (int f = 0; f < 16; f++) {
            int base = f * 16 + c0l;
            A4[f][0] = *reinterpret_cast<const uint32_t*>(zb + r0l * DDIM + base);
            A4[f][1] = *reinterpret_cast<const uint32_t*>(zb + (r0l + 8) * DDIM + base);
            A4[f][2] = *reinterpret_cast<const uint32_t*>(zb + r0l * DDIM + base + 8);
            A4[f][3] = *reinterpret_cast<const uint32_t*>(zb + (r0l + 8) * DDIM + base + 8);
        }
    }

    const int row0 = rowbase + rowg * 16 + r0l;
    const float Av0 = g_A[row0], Av1 = g_A[row0 + 8];
    float tv[2][3]; int tj[2][3];
    #pragma unroll
    for (int ri = 0; ri < 2; ri++)
        #pragma unroll
        for (int k = 0; k < 3; k++) { tv[ri][k] = INFINITY; tj[ri][k] = 0; }

    float acc[4][4];                     // N=32 per warp: 4 n8-frags
    #pragma unroll
    for (int nf = 0; nf < 4; nf++)
        #pragma unroll
        for (int q = 0; q < 4; q++) acc[nf][q] = 0.f;

    const int nrow = (l & 7) + (l & 8);
    const int ksel = (l >> 4) & 1;
    const float2 zz2 = make_float2(0.f, 0.f);

    int slot = 0, pslot = 2;
    for (int si = 0; si < NSI; si++) {
        CP_WAIT1();
        __syncthreads();
        if (si + 2 < NSI) loadB_stage(sbB, si + 2, pslot, tid);
        CP_COMMIT();

        // embedded one-hot zeroing: stage si zeroes row (rowbase + si>>1),
        // col half (si&1)*4096 .. +4095 : 2048 float2 over 512 threads
        {
            float2* zp = reinterpret_cast<float2*>(
                out + O_ENC + (long)(rowbase + (si >> 1)) * NE + (si & 1) * 4096);
            #pragma unroll
            for (int r = 0; r < 4; r++) zp[r * 512 + tid] = zz2;
        }

        const uint32_t stb = sbB + (uint32_t)slot * STG_BYTES;
        #pragma unroll
        for (int c4 = 0; c4 < 4; c4++) {
            const int kc = (si & 1) * 4 + c4;
            const uint32_t ckb = stb + (uint32_t)c4 * 4096;
            const uint32_t* f0 = A4[kc * 2];
            const uint32_t* f1 = A4[kc * 2 + 1];
            #pragma unroll
            for (int np = 0; np < 2; np++) {        // this warp's 32 cols
                int n = cg * 32 + np * 16 + nrow;
                uint32_t rowad = ckb + n * 64;
                uint32_t swm = ((n >> 1) & 3);
                uint32_t b0[4], b1[4];
                ldsm4(b0, rowad + (((0 + ksel) ^ swm) << 4));
                ldsm4(b1, rowad + (((2 + ksel) ^ swm) << 4));
                mma_bf16(acc[2 * np],     f0, b0[0], b0[2]);
                mma_bf16(acc[2 * np],     f1, b1[0], b1[2]);
                mma_bf16(acc[2 * np + 1], f0, b0[1], b0[3]);
                mma_bf16(acc[2 * np + 1], f1, b1[1], b1[3]);
            }
        }

        if (si & 1) {        // tile complete: dists + per-row top-3, reset acc
            int jb = (si >> 1) * 64 + cg * 32 + c0l;
            #pragma unroll
            for (int nf = 0; nf < 4; nf++)
                #pragma unroll
                for (int q = 0; q < 4; q++) {
                    float dd = fmaf(-2.f, acc[nf][q], (q & 2) ? Av1 : Av0);
                    top3_ins(tv[q >> 1], tj[q >> 1], dd, jb + nf * 8 + (q & 1));
                    acc[nf][q] = 0.f;
                }
        }
        slot = (slot == 2) ? 0 : slot + 1;
        pslot = (pslot == 2) ? 0 : pslot + 1;
    }

    const int sub = cg * 4 + (l & 3);    // 8 subslots
    #pragma unroll
    for (int ri = 0; ri < 2; ri++) {
        int base = (row0 + ri * 8) * NCAND + sub * 3;
        g_cand[base] = tj[ri][0]; g_cand[base + 1] = tj[ri][1]; g_cand[base + 2] = tj[ri][2];
    }
}

// ---------------- K2: exact fp32 rescore (coalesced z load) ----------------
__global__ void __launch_bounds__(256) vq_rescore(const float* __restrict__ z,
                                                  const float* __restrict__ emb,
                                                  float* __restrict__ out) {
    __shared__ float zs[8][260];
    const int t = threadIdx.x;
    const int warp = t >> 5, lane = t & 31;
    const int r0 = blockIdx.x * 8;
    const long zbase = (long)(r0 >> 10) * 262144L + (r0 & 1023);

    #pragma unroll
    for (int it = 0; it < 8; it++) {
        int idx = it * 256 + t;
        int c = idx >> 3, rl = idx & 7;
        zs[rl][c] = z[zbase + rl + (long)c * 1024L];
    }
    __syncthreads();

    const int row = r0 + warp;
    const float A = g_A[row];
    float d1 = INFINITY, d2 = INFINITY; int i1 = 0, i2 = 0;

    if (lane < NCAND) {
        int j = g_cand[row * NCAND + lane];
        const float* ep = emb + (long)j * DDIM;
        float dot = 0.f;
        #pragma unroll 8
        for (int c = 0; c < DDIM; c++) dot = fmaf(zs[warp][c], ep[c], dot);
        ins2(d1, i1, d2, i2, fmaf(-2.f, dot, A), j);
    }
    #pragma unroll
    for (int off = 16; off >= 1; off >>= 1) {
        float od1 = __shfl_xor_sync(0xffffffffu, d1, off);
        int   oi1 = __shfl_xor_sync(0xffffffffu, i1, off);
        float od2 = __shfl_xor_sync(0xffffffffu, d2, off);
        int   oi2 = __shfl_xor_sync(0xffffffffu, i2, off);
        merge2(d1, i1, d2, i2, od1, oi1, od2, oi2);
    }
    if (lane == 0) {
        out[O_ENC + (long)row * NE + i1] = 1.0f;
        out[O_MIN + row] = (float)i1;
        out[O_SEC + row] = (float)i2;
        atomicAdd(&g_counts[i1], 1);
    }
}

// ---------------- K3: z_q + loss ----------------
__global__ void vq_zq(const float* __restrict__ z, const float* __restrict__ emb,
                      float* __restrict__ out) {
    int row = blockIdx.x * blockDim.x + threadIdx.x;
    int i1 = (int)out[O_MIN + row];
    const long zoff = (long)(row >> 10) * 262144L + (row & 1023);
    const float* e = emb + (long)i1 * DDIM;
    double ls = 0.0;
    #pragma unroll 8
    for (int c = 0; c < DDIM; c++) {
        float v = e[c];
        long a = zoff + (long)c * 1024L;
        float diff = v - z[a];
        ls += (double)diff * (double)diff;
        out[O_ZQ + a] = v;
    }
    atomicAdd(&g_loss, ls);
}

// ---------------- K4: scalars ----------------
__global__ void vq_entropy() {
    __shared__ double sh[256];
    int t = threadIdx.x;
    int j = blockIdx.x * 256 + t;
    double p = (double)g_counts[j] / 16384.0;
    sh[t] = p * log(p + 1e-10);
    __syncthreads();
    for (int off = 128; off > 0; off >>= 1) {
        if (t < off) sh[t] += sh[t + off];
        __syncthreads();
    }
    if (t == 0) atomicAdd(&g_H, sh[0]);
}
__global__ void vq_final(float* __restrict__ out) {
    out[O_PERP] = (float)exp(-g_H);
    out[O_LOSS] = (float)(1.25 * g_loss / 4194304.0);
}

// ---------------------------------------------------------------------------
extern "C" void kernel_launch(void* const* d_in, const int* in_sizes, int n_in,
                              void* d_out, int out_size) {
    const float* z   = (const float*)d_in[0];
    const float* emb = (const float*)d_in[1];
    float* out = (float*)d_out;

    cudaFuncSetAttribute(vq_gemm, cudaFuncAttributeMaxDynamicSharedMemorySize, SMEM_TOT);
    vq_init<<<R_TOT / 256, 256>>>();
    vq_prep_emb<<<(NE * DDIM / 4) / 256, 256>>>(emb);
    vq_prep_z<<<4096, 256>>>(z);
    vq_gemm<<<128, 512, SMEM_TOT>>>(out);
    vq_rescore<<<R_TOT / 8, 256>>>(z, emb, out);
    vq_zq<<<R_TOT / 256, 256>>>(z, emb, out);
    vq_entropy<<<NE / 256, 256>>>();
    vq_final<<<1, 1>>>(out);
}